// round 3
// baseline (speedup 1.0000x reference)
#include <cuda_runtime.h>
#include <cuda_bf16.h>

#define N_NODES 50000
#define N_EDGES 1600000
#define HID 128
#define N_GRAPHS 64
#define LN_EPS 1e-5f

// ---------------- device scratch (static, no allocation) ----------------
__device__ int   g_deg[N_NODES];
__device__ int   g_rowstart[N_NODES + 1];
__device__ int   g_cursor[N_NODES];
__device__ int   g_csr[N_EDGES];
__device__ float g_invdeg[N_NODES];
__device__ float g_agg[N_NODES * HID];
__device__ float g_bufA[N_NODES * HID];
__device__ float g_bufB[N_NODES * HID];
__device__ float g_cnt[N_GRAPHS];

// ---------------- init: zero counters + graph output region ----------------
__global__ void k_init(float* dout_graph) {
    int i = blockIdx.x * blockDim.x + threadIdx.x;
    if (i < N_NODES) { g_deg[i] = 0; g_cursor[i] = 0; }
    if (i < N_GRAPHS * HID) dout_graph[i] = 0.f;
    if (i < N_GRAPHS) g_cnt[i] = 0.f;
}

// ---------------- degree histogram ----------------
__global__ void k_hist(const int* __restrict__ dst) {
    int i = blockIdx.x * blockDim.x + threadIdx.x;
    if (i < N_EDGES) atomicAdd(&g_deg[dst[i]], 1);
}

// ---------------- single-block inclusive scan -> row_start, inv_deg ----------------
__global__ void k_scan() {
    __shared__ int s[1024];
    __shared__ int carry;
    int tid = threadIdx.x;
    if (tid == 0) { carry = 0; g_rowstart[0] = 0; }
    __syncthreads();
    for (int base = 0; base < N_NODES; base += 1024) {
        int idx = base + tid;
        int v = (idx < N_NODES) ? g_deg[idx] : 0;
        if (idx < N_NODES) g_invdeg[idx] = 1.f / fmaxf((float)v, 1.f);
        s[tid] = v;
        __syncthreads();
        for (int off = 1; off < 1024; off <<= 1) {
            int t = s[tid];
            if (tid >= off) t += s[tid - off];
            __syncthreads();
            s[tid] = t;
            __syncthreads();
        }
        int c = carry;
        if (idx < N_NODES) g_rowstart[idx + 1] = c + s[tid];
        __syncthreads();
        if (tid == 1023) carry = c + s[1023];
        __syncthreads();
    }
}

// ---------------- CSR fill ----------------
__global__ void k_fill(const int* __restrict__ src, const int* __restrict__ dst) {
    int i = blockIdx.x * blockDim.x + threadIdx.x;
    if (i < N_EDGES) {
        int d = dst[i];
        int p = atomicAdd(&g_cursor[d], 1);
        g_csr[g_rowstart[d] + p] = src[i];
    }
}

// ---------------- mean-neighbor aggregation: warp per node ----------------
__global__ void k_agg(const float* __restrict__ x) {
    int gw = (blockIdx.x * blockDim.x + threadIdx.x) >> 5;
    int lane = threadIdx.x & 31;
    if (gw >= N_NODES) return;
    int beg = g_rowstart[gw], end = g_rowstart[gw + 1];
    const float4* xv = (const float4*)x;
    float4 a0 = {0, 0, 0, 0}, a1 = a0, a2 = a0, a3 = a0;
    for (int e = beg; e < end; e += 32) {
        int n = (e + lane < end) ? g_csr[e + lane] : 0;
        int c = min(32, end - e);
        int j = 0;
        for (; j + 4 <= c; j += 4) {
            int s0 = __shfl_sync(0xffffffffu, n, j);
            int s1 = __shfl_sync(0xffffffffu, n, j + 1);
            int s2 = __shfl_sync(0xffffffffu, n, j + 2);
            int s3 = __shfl_sync(0xffffffffu, n, j + 3);
            float4 v0 = xv[s0 * 32 + lane];
            float4 v1 = xv[s1 * 32 + lane];
            float4 v2 = xv[s2 * 32 + lane];
            float4 v3 = xv[s3 * 32 + lane];
            a0.x += v0.x; a0.y += v0.y; a0.z += v0.z; a0.w += v0.w;
            a1.x += v1.x; a1.y += v1.y; a1.z += v1.z; a1.w += v1.w;
            a2.x += v2.x; a2.y += v2.y; a2.z += v2.z; a2.w += v2.w;
            a3.x += v3.x; a3.y += v3.y; a3.z += v3.z; a3.w += v3.w;
        }
        for (; j < c; j++) {
            int s0 = __shfl_sync(0xffffffffu, n, j);
            float4 v0 = xv[s0 * 32 + lane];
            a0.x += v0.x; a0.y += v0.y; a0.z += v0.z; a0.w += v0.w;
        }
    }
    float sc = g_invdeg[gw];
    float4 r;
    r.x = (a0.x + a1.x + a2.x + a3.x) * sc;
    r.y = (a0.y + a1.y + a2.y + a3.y) * sc;
    r.z = (a0.z + a1.z + a2.z + a3.z) * sc;
    r.w = (a0.w + a1.w + a2.w + a3.w) * sc;
    ((float4*)g_agg)[gw * 32 + lane] = r;
}

// ---------------- fused GEMM (K=256: [agg;x] @ [Wn;Wr] + bn) + LayerNorm + ReLU ----------------
// block: 256 threads, tile M=64 x N=128. thread tile 4 rows x 8 cols.
__global__ void __launch_bounds__(256) k_gemm_ln(
    const float* __restrict__ xin,
    const float* __restrict__ Wn, const float* __restrict__ bnp,
    const float* __restrict__ Wr,
    const float* __restrict__ gm, const float* __restrict__ bt,
    float* __restrict__ xout)
{
    __shared__ float As[16][65];
    __shared__ float Ws[16][128];
    int tid = threadIdx.x;
    int m0 = blockIdx.x * 64;
    int cx = tid & 15;        // column group: cols cx*8 .. cx*8+7
    int ry = tid >> 4;        // row group: rows ry*4 .. ry*4+3
    float acc[4][8];
#pragma unroll
    for (int i = 0; i < 4; i++)
#pragma unroll
        for (int j = 0; j < 8; j++) acc[i][j] = 0.f;

    for (int kc = 0; kc < 16; kc++) {
        int kbase = kc * 16;
        // load A tile 64x16 (k<128 -> agg, else xin)
#pragma unroll
        for (int i = 0; i < 4; i++) {
            int idx = tid + i * 256;
            int r = idx >> 4, kl = idx & 15;
            int row = m0 + r, k = kbase + kl;
            float v = 0.f;
            if (row < N_NODES)
                v = (k < 128) ? g_agg[row * 128 + k] : xin[row * 128 + (k - 128)];
            As[kl][r] = v;
        }
        // load W tile 16x128 (k<128 -> Wn, else Wr)
#pragma unroll
        for (int i = 0; i < 8; i++) {
            int idx = tid + i * 256;
            int kl = idx >> 7, c = idx & 127;
            int k = kbase + kl;
            Ws[kl][c] = (k < 128) ? Wn[k * 128 + c] : Wr[(k - 128) * 128 + c];
        }
        __syncthreads();
#pragma unroll
        for (int kl = 0; kl < 16; kl++) {
            float wv[8];
#pragma unroll
            for (int j = 0; j < 8; j++) wv[j] = Ws[kl][cx * 8 + j];
            float av[4];
#pragma unroll
            for (int i = 0; i < 4; i++) av[i] = As[kl][ry * 4 + i];
#pragma unroll
            for (int i = 0; i < 4; i++)
#pragma unroll
                for (int j = 0; j < 8; j++) acc[i][j] = fmaf(av[i], wv[j], acc[i][j]);
        }
        __syncthreads();
    }

    // epilogue: +bn, LayerNorm over 128 cols (16 threads per row), ReLU
    float bnv[8], gv[8], bv[8];
#pragma unroll
    for (int j = 0; j < 8; j++) {
        int c = cx * 8 + j;
        bnv[j] = bnp[c]; gv[j] = gm[c]; bv[j] = bt[c];
    }
#pragma unroll
    for (int i = 0; i < 4; i++) {
        float s = 0.f;
#pragma unroll
        for (int j = 0; j < 8; j++) { acc[i][j] += bnv[j]; s += acc[i][j]; }
        s += __shfl_xor_sync(0xffffffffu, s, 1);
        s += __shfl_xor_sync(0xffffffffu, s, 2);
        s += __shfl_xor_sync(0xffffffffu, s, 4);
        s += __shfl_xor_sync(0xffffffffu, s, 8);
        float mean = s * (1.f / 128.f);
        float sq = 0.f;
#pragma unroll
        for (int j = 0; j < 8; j++) { float d = acc[i][j] - mean; sq += d * d; }
        sq += __shfl_xor_sync(0xffffffffu, sq, 1);
        sq += __shfl_xor_sync(0xffffffffu, sq, 2);
        sq += __shfl_xor_sync(0xffffffffu, sq, 4);
        sq += __shfl_xor_sync(0xffffffffu, sq, 8);
        float rstd = rsqrtf(sq * (1.f / 128.f) + LN_EPS);
        int row = m0 + ry * 4 + i;
        if (row < N_NODES) {
            float4 o0, o1;
            float o[8];
#pragma unroll
            for (int j = 0; j < 8; j++)
                o[j] = fmaxf((acc[i][j] - mean) * rstd * gv[j] + bv[j], 0.f);
            o0.x = o[0]; o0.y = o[1]; o0.z = o[2]; o0.w = o[3];
            o1.x = o[4]; o1.y = o[5]; o1.z = o[6]; o1.w = o[7];
            float* base = xout + row * 128 + cx * 8;
            ((float4*)base)[0] = o0;
            ((float4*)base)[1] = o1;
        }
    }
}

// ---------------- graph mean pool: block = 64-node chunk, thread = feature ----------------
__global__ void k_pool(const float* __restrict__ node, const int* __restrict__ batch,
                       float* __restrict__ gsum) {
    int f = threadIdx.x;  // 128
    int n0 = blockIdx.x * 64;
    if (n0 >= N_NODES) return;
    int n1 = min(n0 + 64, N_NODES);
    float acc = 0.f;
    int cnt = 0;
    int cur = batch[n0];
    for (int n = n0; n < n1; n++) {
        int b = batch[n];
        if (b != cur) {
            atomicAdd(&gsum[cur * 128 + f], acc);
            if (f == 0) atomicAdd(&g_cnt[cur], (float)cnt);
            acc = 0.f; cnt = 0; cur = b;
        }
        acc += node[n * 128 + f];
        cnt++;
    }
    atomicAdd(&gsum[cur * 128 + f], acc);
    if (f == 0) atomicAdd(&g_cnt[cur], (float)cnt);
}

__global__ void k_div(float* __restrict__ gout) {
    int i = blockIdx.x * blockDim.x + threadIdx.x;
    if (i < N_GRAPHS * HID) {
        int g = i >> 7;
        gout[i] = gout[i] / fmaxf(g_cnt[g], 1.f);
    }
}

// ---------------- launch ----------------
extern "C" void kernel_launch(void* const* d_in, const int* in_sizes, int n_in,
                              void* d_out, int out_size) {
    const float* x     = (const float*)d_in[0];
    const float* Wn    = (const float*)d_in[1];
    const float* bn    = (const float*)d_in[2];
    const float* Wr    = (const float*)d_in[3];
    const float* gamma = (const float*)d_in[4];
    const float* beta  = (const float*)d_in[5];
    const int*   ei    = (const int*)d_in[6];
    const int*   batch = (const int*)d_in[7];
    float* out = (float*)d_out;

    float* out_graph = out;                    // [64, 128]
    float* out_node  = out + N_GRAPHS * HID;   // [50000, 128]

    const int* src = ei;
    const int* dst = ei + N_EDGES;

    // CSR build (graph is layer-invariant)
    k_init<<<(N_NODES + 255) / 256, 256>>>(out_graph);
    k_hist<<<(N_EDGES + 255) / 256, 256>>>(dst);
    k_scan<<<1, 1024>>>();
    k_fill<<<(N_EDGES + 255) / 256, 256>>>(src, dst);

    int aggGrid = (N_NODES * 32 + 255) / 256;       // warp per node
    int gemmGrid = (N_NODES + 63) / 64;

    // get raw pointers to the ping-pong buffers via device symbols is not needed:
    // we reference them directly as globals inside kernels, but the gemm output /
    // agg input alternates, so pass pointers obtained from the symbols.
    // (static __device__ arrays: take their address in device code only; here we
    //  use cudaGetSymbolAddress-free approach by dedicated wrappers below.)

    // layer 0: x -> bufA
    k_agg<<<aggGrid, 256>>>(x);
    {
        float* bufA;
        cudaGetSymbolAddress((void**)&bufA, g_bufA);
        k_gemm_ln<<<gemmGrid, 256>>>(x, Wn, bn, Wr, gamma, beta, bufA);
    }
    // layer 1: bufA -> bufB
    {
        float *bufA, *bufB;
        cudaGetSymbolAddress((void**)&bufA, g_bufA);
        cudaGetSymbolAddress((void**)&bufB, g_bufB);
        k_agg<<<aggGrid, 256>>>(bufA);
        k_gemm_ln<<<gemmGrid, 256>>>(bufA, Wn + 128 * 128, bn + 128, Wr + 128 * 128,
                                     gamma + 128, beta + 128, bufB);
    }
    // layer 2: bufB -> out_node
    {
        float* bufB;
        cudaGetSymbolAddress((void**)&bufB, g_bufB);
        k_agg<<<aggGrid, 256>>>(bufB);
        k_gemm_ln<<<gemmGrid, 256>>>(bufB, Wn + 2 * 128 * 128, bn + 2 * 128,
                                     Wr + 2 * 128 * 128, gamma + 2 * 128, beta + 2 * 128,
                                     out_node);
    }
    // pooling
    k_pool<<<(N_NODES + 63) / 64, 128>>>(out_node, batch, out_graph);
    k_div<<<(N_GRAPHS * HID + 255) / 256, 256>>>(out_graph);
}

// round 4
// speedup vs baseline: 1.3409x; 1.3409x over previous
#include <cuda_runtime.h>
#include <cuda_bf16.h>

#define N_NODES 50000
#define N_EDGES 1600000
#define HID 128
#define N_GRAPHS 64
#define LN_EPS 1e-5f
#define NBLK ((N_NODES + 255) / 256)   // 196

// ---------------- device scratch (static, no allocation) ----------------
__device__ int   g_deg[N_NODES];
__device__ int   g_rowstart[N_NODES + 1];
__device__ int   g_cursor[N_NODES];
__device__ int   g_csr[N_EDGES];
__device__ float g_invdeg[N_NODES];
__device__ float g_agg[N_NODES * HID];
__device__ float g_bufA[N_NODES * HID];
__device__ float g_bufB[N_NODES * HID];
__device__ float g_cnt[N_GRAPHS];
__device__ int   g_blocksum[NBLK];

// ---------------- f32x2 packed helpers ----------------
__device__ __forceinline__ unsigned long long pack2(float lo, float hi) {
    unsigned long long r;
    asm("mov.b64 %0, {%1, %2};" : "=l"(r) : "f"(lo), "f"(hi));
    return r;
}
__device__ __forceinline__ void unpack2(unsigned long long v, float& lo, float& hi) {
    asm("mov.b64 {%0, %1}, %2;" : "=f"(lo), "=f"(hi) : "l"(v));
}
__device__ __forceinline__ void ffma2(unsigned long long& d, unsigned long long a,
                                      unsigned long long b) {
    asm("fma.rn.f32x2 %0, %1, %2, %0;" : "+l"(d) : "l"(a), "l"(b));
}

// ---------------- init: zero counters + graph output region ----------------
__global__ void k_init(float* dout_graph) {
    int i = blockIdx.x * blockDim.x + threadIdx.x;
    if (i < N_NODES) { g_deg[i] = 0; g_cursor[i] = 0; }
    if (i < N_GRAPHS * HID) dout_graph[i] = 0.f;
    if (i < N_GRAPHS) g_cnt[i] = 0.f;
}

// ---------------- degree histogram ----------------
__global__ void k_hist(const int* __restrict__ dst) {
    int i = blockIdx.x * blockDim.x + threadIdx.x;
    if (i < N_EDGES) atomicAdd(&g_deg[dst[i]], 1);
}

// ---------------- scan stage 1: per-block degree sums ----------------
__global__ void k_blocksum() {
    int b = blockIdx.x, t = threadIdx.x;
    int i = b * 256 + t;
    int v = (i < N_NODES) ? g_deg[i] : 0;
#pragma unroll
    for (int o = 16; o; o >>= 1) v += __shfl_down_sync(0xffffffffu, v, o);
    __shared__ int ws[8];
    if ((t & 31) == 0) ws[t >> 5] = v;
    __syncthreads();
    if (t < 8) {
        int s = ws[t];
#pragma unroll
        for (int o = 4; o; o >>= 1) s += __shfl_down_sync(0xffu, s, o);
        if (t == 0) g_blocksum[b] = s;
    }
}

// ---------------- scan stage 2: exclusive scan of block sums (1 block) ----------------
__global__ void k_scanblocksums() {
    int t = threadIdx.x;
    int v = (t < NBLK) ? g_blocksum[t] : 0;
    int lane = t & 31, w = t >> 5;
    int s = v;
#pragma unroll
    for (int o = 1; o < 32; o <<= 1) {
        int u = __shfl_up_sync(0xffffffffu, s, o);
        if (lane >= o) s += u;
    }
    __shared__ int wsum[8];
    if (lane == 31) wsum[w] = s;
    __syncthreads();
    if (t < 8) {
        int x = wsum[t];
#pragma unroll
        for (int o = 1; o < 8; o <<= 1) {
            int u = __shfl_up_sync(0xffu, x, o);
            if (t >= o) x += u;
        }
        wsum[t] = x;
    }
    __syncthreads();
    int incl = s + (w ? wsum[w - 1] : 0);
    if (t < NBLK) g_blocksum[t] = incl - v;  // exclusive
}

// ---------------- scan stage 3: rowstart + invdeg ----------------
__global__ void k_rowstart() {
    int b = blockIdx.x, t = threadIdx.x;
    int i = b * 256 + t;
    int v = (i < N_NODES) ? g_deg[i] : 0;
    if (i < N_NODES) g_invdeg[i] = 1.f / fmaxf((float)v, 1.f);
    int lane = t & 31, w = t >> 5;
    int s = v;
#pragma unroll
    for (int o = 1; o < 32; o <<= 1) {
        int u = __shfl_up_sync(0xffffffffu, s, o);
        if (lane >= o) s += u;
    }
    __shared__ int wsum[8];
    if (lane == 31) wsum[w] = s;
    __syncthreads();
    if (t < 8) {
        int x = wsum[t];
#pragma unroll
        for (int o = 1; o < 8; o <<= 1) {
            int u = __shfl_up_sync(0xffu, x, o);
            if (t >= o) x += u;
        }
        wsum[t] = x;
    }
    __syncthreads();
    int incl = s + (w ? wsum[w - 1] : 0) + g_blocksum[b];
    if (i < N_NODES) g_rowstart[i + 1] = incl;
    if (i == 0) g_rowstart[0] = 0;
}

// ---------------- CSR fill ----------------
__global__ void k_fill(const int* __restrict__ src, const int* __restrict__ dst) {
    int i = blockIdx.x * blockDim.x + threadIdx.x;
    if (i < N_EDGES) {
        int d = dst[i];
        int p = atomicAdd(&g_cursor[d], 1);
        g_csr[g_rowstart[d] + p] = src[i];
    }
}

// ---------------- mean-neighbor aggregation: warp per node ----------------
__global__ void k_agg(const float* __restrict__ x) {
    int gw = (blockIdx.x * blockDim.x + threadIdx.x) >> 5;
    int lane = threadIdx.x & 31;
    if (gw >= N_NODES) return;
    int beg = g_rowstart[gw], end = g_rowstart[gw + 1];
    const float4* xv = (const float4*)x;
    float4 a0 = {0, 0, 0, 0}, a1 = a0, a2 = a0, a3 = a0;
    for (int e = beg; e < end; e += 32) {
        int n = (e + lane < end) ? g_csr[e + lane] : 0;
        int c = min(32, end - e);
        int j = 0;
        for (; j + 4 <= c; j += 4) {
            int s0 = __shfl_sync(0xffffffffu, n, j);
            int s1 = __shfl_sync(0xffffffffu, n, j + 1);
            int s2 = __shfl_sync(0xffffffffu, n, j + 2);
            int s3 = __shfl_sync(0xffffffffu, n, j + 3);
            float4 v0 = xv[s0 * 32 + lane];
            float4 v1 = xv[s1 * 32 + lane];
            float4 v2 = xv[s2 * 32 + lane];
            float4 v3 = xv[s3 * 32 + lane];
            a0.x += v0.x; a0.y += v0.y; a0.z += v0.z; a0.w += v0.w;
            a1.x += v1.x; a1.y += v1.y; a1.z += v1.z; a1.w += v1.w;
            a2.x += v2.x; a2.y += v2.y; a2.z += v2.z; a2.w += v2.w;
            a3.x += v3.x; a3.y += v3.y; a3.z += v3.z; a3.w += v3.w;
        }
        for (; j < c; j++) {
            int s0 = __shfl_sync(0xffffffffu, n, j);
            float4 v0 = xv[s0 * 32 + lane];
            a0.x += v0.x; a0.y += v0.y; a0.z += v0.z; a0.w += v0.w;
        }
    }
    float sc = g_invdeg[gw];
    float4 r;
    r.x = (a0.x + a1.x + a2.x + a3.x) * sc;
    r.y = (a0.y + a1.y + a2.y + a3.y) * sc;
    r.z = (a0.z + a1.z + a2.z + a3.z) * sc;
    r.w = (a0.w + a1.w + a2.w + a3.w) * sc;
    ((float4*)g_agg)[gw * 32 + lane] = r;
}

// ---------------- fused GEMM (K=256: [agg;x] @ [Wn;Wr] + bn) + LayerNorm + ReLU ----------------
// block: 256 threads, tile M=64 x N=128. thread: 4 rows (ry*4..+3) x 4 col PAIRS.
// thread cx owns column pairs (2cx+32jp, 2cx+1+32jp), jp=0..3 -> packed f32x2 FMA.
__global__ void __launch_bounds__(256) k_gemm_ln(
    const float* __restrict__ xin,
    const float* __restrict__ Wn, const float* __restrict__ bnp,
    const float* __restrict__ Wr,
    const float* __restrict__ gm, const float* __restrict__ bt,
    float* __restrict__ xout)
{
    __shared__ float As[16][68];     // row stride 272B (16B aligned)
    __shared__ float Ws[16][128];    // row stride 512B
    int tid = threadIdx.x;
    int m0 = blockIdx.x * 64;
    int cx = tid & 15;
    int ry = tid >> 4;
    unsigned long long acc2[4][4];
#pragma unroll
    for (int i = 0; i < 4; i++)
#pragma unroll
        for (int jp = 0; jp < 4; jp++) acc2[i][jp] = 0ull;

    for (int kc = 0; kc < 16; kc++) {
        int kbase = kc * 16;
        // load A tile 64x16 (k<128 -> agg, else xin)
#pragma unroll
        for (int i = 0; i < 4; i++) {
            int idx = tid + i * 256;
            int r = idx >> 4, kl = idx & 15;
            int row = m0 + r, k = kbase + kl;
            float v = 0.f;
            if (row < N_NODES)
                v = (k < 128) ? g_agg[row * 128 + k] : xin[row * 128 + (k - 128)];
            As[kl][r] = v;
        }
        // load W tile 16x128 (k<128 -> Wn, else Wr)
#pragma unroll
        for (int i = 0; i < 8; i++) {
            int idx = tid + i * 256;
            int kl = idx >> 7, c = idx & 127;
            int k = kbase + kl;
            Ws[kl][c] = (k < 128) ? Wn[k * 128 + c] : Wr[(k - 128) * 128 + c];
        }
        __syncthreads();
#pragma unroll
        for (int kl = 0; kl < 16; kl++) {
            float4 av = *(const float4*)&As[kl][ry * 4];
            unsigned long long a0 = pack2(av.x, av.x);
            unsigned long long a1 = pack2(av.y, av.y);
            unsigned long long a2 = pack2(av.z, av.z);
            unsigned long long a3 = pack2(av.w, av.w);
            unsigned long long w0 = *(const unsigned long long*)&Ws[kl][2 * cx];
            unsigned long long w1 = *(const unsigned long long*)&Ws[kl][2 * cx + 32];
            unsigned long long w2 = *(const unsigned long long*)&Ws[kl][2 * cx + 64];
            unsigned long long w3 = *(const unsigned long long*)&Ws[kl][2 * cx + 96];
            ffma2(acc2[0][0], a0, w0); ffma2(acc2[0][1], a0, w1);
            ffma2(acc2[0][2], a0, w2); ffma2(acc2[0][3], a0, w3);
            ffma2(acc2[1][0], a1, w0); ffma2(acc2[1][1], a1, w1);
            ffma2(acc2[1][2], a1, w2); ffma2(acc2[1][3], a1, w3);
            ffma2(acc2[2][0], a2, w0); ffma2(acc2[2][1], a2, w1);
            ffma2(acc2[2][2], a2, w2); ffma2(acc2[2][3], a2, w3);
            ffma2(acc2[3][0], a3, w0); ffma2(acc2[3][1], a3, w1);
            ffma2(acc2[3][2], a3, w2); ffma2(acc2[3][3], a3, w3);
        }
        __syncthreads();
    }

    // epilogue: +bn, LayerNorm over 128 cols (16 threads per row), ReLU
    float2 bn2[4], g2[4], b2[4];
#pragma unroll
    for (int jp = 0; jp < 4; jp++) {
        int c = 2 * cx + 32 * jp;
        bn2[jp] = *(const float2*)&bnp[c];
        g2[jp]  = *(const float2*)&gm[c];
        b2[jp]  = *(const float2*)&bt[c];
    }
#pragma unroll
    for (int i = 0; i < 4; i++) {
        float v[8];
        float s = 0.f;
#pragma unroll
        for (int jp = 0; jp < 4; jp++) {
            float lo, hi;
            unpack2(acc2[i][jp], lo, hi);
            lo += bn2[jp].x; hi += bn2[jp].y;
            v[2 * jp] = lo; v[2 * jp + 1] = hi;
            s += lo + hi;
        }
        s += __shfl_xor_sync(0xffffffffu, s, 1);
        s += __shfl_xor_sync(0xffffffffu, s, 2);
        s += __shfl_xor_sync(0xffffffffu, s, 4);
        s += __shfl_xor_sync(0xffffffffu, s, 8);
        float mean = s * (1.f / 128.f);
        float sq = 0.f;
#pragma unroll
        for (int j = 0; j < 8; j++) { float d = v[j] - mean; sq += d * d; }
        sq += __shfl_xor_sync(0xffffffffu, sq, 1);
        sq += __shfl_xor_sync(0xffffffffu, sq, 2);
        sq += __shfl_xor_sync(0xffffffffu, sq, 4);
        sq += __shfl_xor_sync(0xffffffffu, sq, 8);
        float rstd = rsqrtf(sq * (1.f / 128.f) + LN_EPS);
        int row = m0 + ry * 4 + i;
        if (row < N_NODES) {
            float* base = xout + row * 128;
#pragma unroll
            for (int jp = 0; jp < 4; jp++) {
                float2 o;
                o.x = fmaxf((v[2 * jp]     - mean) * rstd * g2[jp].x + b2[jp].x, 0.f);
                o.y = fmaxf((v[2 * jp + 1] - mean) * rstd * g2[jp].y + b2[jp].y, 0.f);
                *(float2*)&base[2 * cx + 32 * jp] = o;
            }
        }
    }
}

// ---------------- graph mean pool: block = 64-node chunk, thread = feature ----------------
__global__ void k_pool(const float* __restrict__ node, const int* __restrict__ batch,
                       float* __restrict__ gsum) {
    int f = threadIdx.x;  // 128
    int n0 = blockIdx.x * 64;
    if (n0 >= N_NODES) return;
    int n1 = min(n0 + 64, N_NODES);
    float acc = 0.f;
    int cnt = 0;
    int cur = batch[n0];
    for (int n = n0; n < n1; n++) {
        int b = batch[n];
        if (b != cur) {
            atomicAdd(&gsum[cur * 128 + f], acc);
            if (f == 0) atomicAdd(&g_cnt[cur], (float)cnt);
            acc = 0.f; cnt = 0; cur = b;
        }
        acc += node[n * 128 + f];
        cnt++;
    }
    atomicAdd(&gsum[cur * 128 + f], acc);
    if (f == 0) atomicAdd(&g_cnt[cur], (float)cnt);
}

__global__ void k_div(float* __restrict__ gout) {
    int i = blockIdx.x * blockDim.x + threadIdx.x;
    if (i < N_GRAPHS * HID) {
        int g = i >> 7;
        gout[i] = gout[i] / fmaxf(g_cnt[g], 1.f);
    }
}

// ---------------- launch ----------------
extern "C" void kernel_launch(void* const* d_in, const int* in_sizes, int n_in,
                              void* d_out, int out_size) {
    const float* x     = (const float*)d_in[0];
    const float* Wn    = (const float*)d_in[1];
    const float* bn    = (const float*)d_in[2];
    const float* Wr    = (const float*)d_in[3];
    const float* gamma = (const float*)d_in[4];
    const float* beta  = (const float*)d_in[5];
    const int*   ei    = (const int*)d_in[6];
    const int*   batch = (const int*)d_in[7];
    float* out = (float*)d_out;

    float* out_graph = out;                    // [64, 128]
    float* out_node  = out + N_GRAPHS * HID;   // [50000, 128]

    const int* src = ei;
    const int* dst = ei + N_EDGES;

    float *bufA, *bufB;
    cudaGetSymbolAddress((void**)&bufA, g_bufA);
    cudaGetSymbolAddress((void**)&bufB, g_bufB);

    // CSR build (graph is layer-invariant)
    k_init<<<(N_NODES + 255) / 256, 256>>>(out_graph);
    k_hist<<<(N_EDGES + 255) / 256, 256>>>(dst);
    k_blocksum<<<NBLK, 256>>>();
    k_scanblocksums<<<1, 256>>>();
    k_rowstart<<<NBLK, 256>>>();
    k_fill<<<(N_EDGES + 255) / 256, 256>>>(src, dst);

    int aggGrid = (N_NODES * 32 + 255) / 256;       // warp per node
    int gemmGrid = (N_NODES + 63) / 64;

    // layer 0: x -> bufA
    k_agg<<<aggGrid, 256>>>(x);
    k_gemm_ln<<<gemmGrid, 256>>>(x, Wn, bn, Wr, gamma, beta, bufA);
    // layer 1: bufA -> bufB
    k_agg<<<aggGrid, 256>>>(bufA);
    k_gemm_ln<<<gemmGrid, 256>>>(bufA, Wn + 128 * 128, bn + 128, Wr + 128 * 128,
                                 gamma + 128, beta + 128, bufB);
    // layer 2: bufB -> out_node
    k_agg<<<aggGrid, 256>>>(bufB);
    k_gemm_ln<<<gemmGrid, 256>>>(bufB, Wn + 2 * 128 * 128, bn + 2 * 128,
                                 Wr + 2 * 128 * 128, gamma + 2 * 128, beta + 2 * 128,
                                 out_node);
    // pooling
    k_pool<<<(N_NODES + 63) / 64, 128>>>(out_node, batch, out_graph);
    k_div<<<(N_GRAPHS * HID + 255) / 256, 256>>>(out_graph);
}

// round 9
// speedup vs baseline: 1.4819x; 1.1052x over previous
#include <cuda_runtime.h>
#include <cuda_bf16.h>
#include <cuda_fp16.h>

#define N_NODES 50000
#define N_EDGES 1600000
#define HID 128
#define N_GRAPHS 64
#define LN_EPS 1e-5f
#define NBLK ((N_NODES + 255) / 256)   // 196

// ---------------- device scratch (static, no allocation) ----------------
__device__ int    g_deg[N_NODES];
__device__ int    g_rowstart[N_NODES + 1];
__device__ int    g_cursor[N_NODES];
__device__ int    g_csr[N_EDGES];
__device__ float  g_invdeg[N_NODES];
__device__ float  g_agg[N_NODES * HID];
__device__ float  g_bufA[N_NODES * HID];
__device__ float  g_bufB[N_NODES * HID];
__device__ __half g_half[N_NODES * HID];   // fp16 shadow of current layer input
__device__ float  g_cnt[N_GRAPHS];
__device__ int    g_blocksum[NBLK];

// ---------------- f32x2 packed helpers ----------------
__device__ __forceinline__ unsigned long long pack2(float lo, float hi) {
    unsigned long long r;
    asm("mov.b64 %0, {%1, %2};" : "=l"(r) : "f"(lo), "f"(hi));
    return r;
}
__device__ __forceinline__ void unpack2(unsigned long long v, float& lo, float& hi) {
    asm("mov.b64 {%0, %1}, %2;" : "=f"(lo), "=f"(hi) : "l"(v));
}
__device__ __forceinline__ void ffma2(unsigned long long& d, unsigned long long a,
                                      unsigned long long b) {
    asm("fma.rn.f32x2 %0, %1, %2, %0;" : "+l"(d) : "l"(a), "l"(b));
}

// ---------------- init: zero counters + graph output region ----------------
__global__ void k_init(float* dout_graph) {
    int i = blockIdx.x * blockDim.x + threadIdx.x;
    if (i < N_NODES) { g_deg[i] = 0; g_cursor[i] = 0; }
    if (i < N_GRAPHS * HID) dout_graph[i] = 0.f;
    if (i < N_GRAPHS) g_cnt[i] = 0.f;
}

// ---------------- fp32 -> fp16 convert (input x) ----------------
__global__ void k_cvt(const float* __restrict__ x) {
    int i = blockIdx.x * blockDim.x + threadIdx.x;  // 4 elements per thread
    if (i < N_NODES * HID / 4) {
        float4 v = ((const float4*)x)[i];
        __half2 h0 = __floats2half2_rn(v.x, v.y);
        __half2 h1 = __floats2half2_rn(v.z, v.w);
        uint2 p;
        p.x = *(unsigned*)&h0;
        p.y = *(unsigned*)&h1;
        ((uint2*)g_half)[i] = p;
    }
}

// ---------------- degree histogram (4 edges/thread) ----------------
__global__ void k_hist(const int* __restrict__ dst) {
    int i = blockIdx.x * blockDim.x + threadIdx.x;
    if (i < N_EDGES / 4) {
        int4 d = ((const int4*)dst)[i];
        atomicAdd(&g_deg[d.x], 1);
        atomicAdd(&g_deg[d.y], 1);
        atomicAdd(&g_deg[d.z], 1);
        atomicAdd(&g_deg[d.w], 1);
    }
}

// ---------------- scan stage 1: per-block degree sums ----------------
__global__ void k_blocksum() {
    int b = blockIdx.x, t = threadIdx.x;
    int i = b * 256 + t;
    int v = (i < N_NODES) ? g_deg[i] : 0;
#pragma unroll
    for (int o = 16; o; o >>= 1) v += __shfl_down_sync(0xffffffffu, v, o);
    __shared__ int ws[8];
    if ((t & 31) == 0) ws[t >> 5] = v;
    __syncthreads();
    if (t < 8) {
        int s = ws[t];
#pragma unroll
        for (int o = 4; o; o >>= 1) s += __shfl_down_sync(0xffu, s, o);
        if (t == 0) g_blocksum[b] = s;
    }
}

// ---------------- scan stage 2: exclusive scan of block sums (1 block) ----------------
__global__ void k_scanblocksums() {
    int t = threadIdx.x;
    int v = (t < NBLK) ? g_blocksum[t] : 0;
    int lane = t & 31, w = t >> 5;
    int s = v;
#pragma unroll
    for (int o = 1; o < 32; o <<= 1) {
        int u = __shfl_up_sync(0xffffffffu, s, o);
        if (lane >= o) s += u;
    }
    __shared__ int wsum[8];
    if (lane == 31) wsum[w] = s;
    __syncthreads();
    if (t < 8) {
        int x = wsum[t];
#pragma unroll
        for (int o = 1; o < 8; o <<= 1) {
            int u = __shfl_up_sync(0xffu, x, o);
            if (t >= o) x += u;
        }
        wsum[t] = x;
    }
    __syncthreads();
    int incl = s + (w ? wsum[w - 1] : 0);
    if (t < NBLK) g_blocksum[t] = incl - v;  // exclusive
}

// ---------------- scan stage 3: rowstart + invdeg ----------------
__global__ void k_rowstart() {
    int b = blockIdx.x, t = threadIdx.x;
    int i = b * 256 + t;
    int v = (i < N_NODES) ? g_deg[i] : 0;
    if (i < N_NODES) g_invdeg[i] = 1.f / fmaxf((float)v, 1.f);
    int lane = t & 31, w = t >> 5;
    int s = v;
#pragma unroll
    for (int o = 1; o < 32; o <<= 1) {
        int u = __shfl_up_sync(0xffffffffu, s, o);
        if (lane >= o) s += u;
    }
    __shared__ int wsum[8];
    if (lane == 31) wsum[w] = s;
    __syncthreads();
    if (t < 8) {
        int x = wsum[t];
#pragma unroll
        for (int o = 1; o < 8; o <<= 1) {
            int u = __shfl_up_sync(0xffu, x, o);
            if (t >= o) x += u;
        }
        wsum[t] = x;
    }
    __syncthreads();
    int incl = s + (w ? wsum[w - 1] : 0) + g_blocksum[b];
    if (i < N_NODES) g_rowstart[i + 1] = incl;
    if (i == 0) g_rowstart[0] = 0;
}

// ---------------- CSR fill (4 edges/thread) ----------------
__global__ void k_fill(const int* __restrict__ src, const int* __restrict__ dst) {
    int i = blockIdx.x * blockDim.x + threadIdx.x;
    if (i < N_EDGES / 4) {
        int4 d = ((const int4*)dst)[i];
        int4 s = ((const int4*)src)[i];
        int p;
        p = atomicAdd(&g_cursor[d.x], 1); g_csr[g_rowstart[d.x] + p] = s.x;
        p = atomicAdd(&g_cursor[d.y], 1); g_csr[g_rowstart[d.y] + p] = s.y;
        p = atomicAdd(&g_cursor[d.z], 1); g_csr[g_rowstart[d.z] + p] = s.z;
        p = atomicAdd(&g_cursor[d.w], 1); g_csr[g_rowstart[d.w] + p] = s.w;
    }
}

// ---------------- mean-neighbor aggregation from fp16 shadow: warp per node ----------------
// lane owns features [lane*4, lane*4+4): loads uint2 (4 halves, 8B) per neighbor,
// accumulates fp32, writes float4 to g_agg.
__device__ __forceinline__ void acc4h(float4& a, uint2 p) {
    __half2 h0 = *(__half2*)&p.x;
    __half2 h1 = *(__half2*)&p.y;
    float2 f0 = __half22float2(h0);
    float2 f1 = __half22float2(h1);
    a.x += f0.x; a.y += f0.y; a.z += f1.x; a.w += f1.y;
}

__global__ void k_agg() {
    int gw = (blockIdx.x * blockDim.x + threadIdx.x) >> 5;
    int lane = threadIdx.x & 31;
    if (gw >= N_NODES) return;
    int beg = g_rowstart[gw], end = g_rowstart[gw + 1];
    const uint2* xh = (const uint2*)g_half;   // 32 uint2 per row
    float4 a0 = {0, 0, 0, 0}, a1 = a0, a2 = a0, a3 = a0;
    for (int e = beg; e < end; e += 32) {
        int n = (e + lane < end) ? g_csr[e + lane] : 0;
        int c = min(32, end - e);
        int j = 0;
        for (; j + 4 <= c; j += 4) {
            int s0 = __shfl_sync(0xffffffffu, n, j);
            int s1 = __shfl_sync(0xffffffffu, n, j + 1);
            int s2 = __shfl_sync(0xffffffffu, n, j + 2);
            int s3 = __shfl_sync(0xffffffffu, n, j + 3);
            uint2 v0 = xh[s0 * 32 + lane];
            uint2 v1 = xh[s1 * 32 + lane];
            uint2 v2 = xh[s2 * 32 + lane];
            uint2 v3 = xh[s3 * 32 + lane];
            acc4h(a0, v0); acc4h(a1, v1); acc4h(a2, v2); acc4h(a3, v3);
        }
        for (; j < c; j++) {
            int s0 = __shfl_sync(0xffffffffu, n, j);
            acc4h(a0, xh[s0 * 32 + lane]);
        }
    }
    float sc = g_invdeg[gw];
    float4 r;
    r.x = (a0.x + a1.x + a2.x + a3.x) * sc;
    r.y = (a0.y + a1.y + a2.y + a3.y) * sc;
    r.z = (a0.z + a1.z + a2.z + a3.z) * sc;
    r.w = (a0.w + a1.w + a2.w + a3.w) * sc;
    ((float4*)g_agg)[gw * 32 + lane] = r;
}

// ---------------- fused GEMM (K=256: [agg;x] @ [Wn;Wr] + bn) + LayerNorm + ReLU ----------------
// block: 256 threads, tile M=64 x N=128. thread: 4 rows x 4 col pairs (f32x2 FMA).
// Optionally dual-writes an fp16 shadow of the output for the next layer's agg.
__global__ void __launch_bounds__(256) k_gemm_ln(
    const float* __restrict__ xin,
    const float* __restrict__ Wn, const float* __restrict__ bnp,
    const float* __restrict__ Wr,
    const float* __restrict__ gm, const float* __restrict__ bt,
    float* __restrict__ xout, __half* __restrict__ hout)
{
    __shared__ float As[16][68];
    __shared__ float Ws[16][128];
    int tid = threadIdx.x;
    int m0 = blockIdx.x * 64;
    int cx = tid & 15;
    int ry = tid >> 4;
    unsigned long long acc2[4][4];
#pragma unroll
    for (int i = 0; i < 4; i++)
#pragma unroll
        for (int jp = 0; jp < 4; jp++) acc2[i][jp] = 0ull;

    for (int kc = 0; kc < 16; kc++) {
        int kbase = kc * 16;
#pragma unroll
        for (int i = 0; i < 4; i++) {
            int idx = tid + i * 256;
            int r = idx >> 4, kl = idx & 15;
            int row = m0 + r, k = kbase + kl;
            float v = 0.f;
            if (row < N_NODES)
                v = (k < 128) ? g_agg[row * 128 + k] : xin[row * 128 + (k - 128)];
            As[kl][r] = v;
        }
#pragma unroll
        for (int i = 0; i < 8; i++) {
            int idx = tid + i * 256;
            int kl = idx >> 7, c = idx & 127;
            int k = kbase + kl;
            Ws[kl][c] = (k < 128) ? Wn[k * 128 + c] : Wr[(k - 128) * 128 + c];
        }
        __syncthreads();
#pragma unroll
        for (int kl = 0; kl < 16; kl++) {
            float4 av = *(const float4*)&As[kl][ry * 4];
            unsigned long long a0 = pack2(av.x, av.x);
            unsigned long long a1 = pack2(av.y, av.y);
            unsigned long long a2 = pack2(av.z, av.z);
            unsigned long long a3 = pack2(av.w, av.w);
            unsigned long long w0 = *(const unsigned long long*)&Ws[kl][2 * cx];
            unsigned long long w1 = *(const unsigned long long*)&Ws[kl][2 * cx + 32];
            unsigned long long w2 = *(const unsigned long long*)&Ws[kl][2 * cx + 64];
            unsigned long long w3 = *(const unsigned long long*)&Ws[kl][2 * cx + 96];
            ffma2(acc2[0][0], a0, w0); ffma2(acc2[0][1], a0, w1);
            ffma2(acc2[0][2], a0, w2); ffma2(acc2[0][3], a0, w3);
            ffma2(acc2[1][0], a1, w0); ffma2(acc2[1][1], a1, w1);
            ffma2(acc2[1][2], a1, w2); ffma2(acc2[1][3], a1, w3);
            ffma2(acc2[2][0], a2, w0); ffma2(acc2[2][1], a2, w1);
            ffma2(acc2[2][2], a2, w2); ffma2(acc2[2][3], a2, w3);
            ffma2(acc2[3][0], a3, w0); ffma2(acc2[3][1], a3, w1);
            ffma2(acc2[3][2], a3, w2); ffma2(acc2[3][3], a3, w3);
        }
        __syncthreads();
    }

    float2 bn2[4], g2[4], b2[4];
#pragma unroll
    for (int jp = 0; jp < 4; jp++) {
        int c = 2 * cx + 32 * jp;
        bn2[jp] = *(const float2*)&bnp[c];
        g2[jp]  = *(const float2*)&gm[c];
        b2[jp]  = *(const float2*)&bt[c];
    }
#pragma unroll
    for (int i = 0; i < 4; i++) {
        float v[8];
        float s = 0.f;
#pragma unroll
        for (int jp = 0; jp < 4; jp++) {
            float lo, hi;
            unpack2(acc2[i][jp], lo, hi);
            lo += bn2[jp].x; hi += bn2[jp].y;
            v[2 * jp] = lo; v[2 * jp + 1] = hi;
            s += lo + hi;
        }
        s += __shfl_xor_sync(0xffffffffu, s, 1);
        s += __shfl_xor_sync(0xffffffffu, s, 2);
        s += __shfl_xor_sync(0xffffffffu, s, 4);
        s += __shfl_xor_sync(0xffffffffu, s, 8);
        float mean = s * (1.f / 128.f);
        float sq = 0.f;
#pragma unroll
        for (int j = 0; j < 8; j++) { float d = v[j] - mean; sq += d * d; }
        sq += __shfl_xor_sync(0xffffffffu, sq, 1);
        sq += __shfl_xor_sync(0xffffffffu, sq, 2);
        sq += __shfl_xor_sync(0xffffffffu, sq, 4);
        sq += __shfl_xor_sync(0xffffffffu, sq, 8);
        float rstd = rsqrtf(sq * (1.f / 128.f) + LN_EPS);
        int row = m0 + ry * 4 + i;
        if (row < N_NODES) {
            float* base = xout + row * 128;
#pragma unroll
            for (int jp = 0; jp < 4; jp++) {
                float2 o;
                o.x = fmaxf((v[2 * jp]     - mean) * rstd * g2[jp].x + b2[jp].x, 0.f);
                o.y = fmaxf((v[2 * jp + 1] - mean) * rstd * g2[jp].y + b2[jp].y, 0.f);
                *(float2*)&base[2 * cx + 32 * jp] = o;
                if (hout) {
                    __half2 h = __floats2half2_rn(o.x, o.y);
                    *(__half2*)&hout[row * 128 + 2 * cx + 32 * jp] = h;
                }
            }
        }
    }
}

// ---------------- graph mean pool: block = 64-node chunk, thread = feature ----------------
__global__ void k_pool(const float* __restrict__ node, const int* __restrict__ batch,
                       float* __restrict__ gsum) {
    int f = threadIdx.x;  // 128
    int n0 = blockIdx.x * 64;
    if (n0 >= N_NODES) return;
    int n1 = min(n0 + 64, N_NODES);
    float acc = 0.f;
    int cnt = 0;
    int cur = batch[n0];
    for (int n = n0; n < n1; n++) {
        int b = batch[n];
        if (b != cur) {
            atomicAdd(&gsum[cur * 128 + f], acc);
            if (f == 0) atomicAdd(&g_cnt[cur], (float)cnt);
            acc = 0.f; cnt = 0; cur = b;
        }
        acc += node[n * 128 + f];
        cnt++;
    }
    atomicAdd(&gsum[cur * 128 + f], acc);
    if (f == 0) atomicAdd(&g_cnt[cur], (float)cnt);
}

__global__ void k_div(float* __restrict__ gout) {
    int i = blockIdx.x * blockDim.x + threadIdx.x;
    if (i < N_GRAPHS * HID) {
        int g = i >> 7;
        gout[i] = gout[i] / fmaxf(g_cnt[g], 1.f);
    }
}

// ---------------- launch ----------------
extern "C" void kernel_launch(void* const* d_in, const int* in_sizes, int n_in,
                              void* d_out, int out_size) {
    const float* x     = (const float*)d_in[0];
    const float* Wn    = (const float*)d_in[1];
    const float* bn    = (const float*)d_in[2];
    const float* Wr    = (const float*)d_in[3];
    const float* gamma = (const float*)d_in[4];
    const float* beta  = (const float*)d_in[5];
    const int*   ei    = (const int*)d_in[6];
    const int*   batch = (const int*)d_in[7];
    float* out = (float*)d_out;

    float* out_graph = out;                    // [64, 128]
    float* out_node  = out + N_GRAPHS * HID;   // [50000, 128]

    const int* src = ei;
    const int* dst = ei + N_EDGES;

    float *bufA, *bufB;
    __half* halfbuf;
    cudaGetSymbolAddress((void**)&bufA, g_bufA);
    cudaGetSymbolAddress((void**)&bufB, g_bufB);
    cudaGetSymbolAddress((void**)&halfbuf, g_half);

    // CSR build + fp16 shadow of input
    k_init<<<(N_NODES + 255) / 256, 256>>>(out_graph);
    k_cvt<<<(N_NODES * HID / 4 + 255) / 256, 256>>>(x);
    k_hist<<<(N_EDGES / 4 + 255) / 256, 256>>>(dst);
    k_blocksum<<<NBLK, 256>>>();
    k_scanblocksums<<<1, 256>>>();
    k_rowstart<<<NBLK, 256>>>();
    k_fill<<<(N_EDGES / 4 + 255) / 256, 256>>>(src, dst);

    int aggGrid = (N_NODES * 32 + 255) / 256;       // warp per node
    int gemmGrid = (N_NODES + 63) / 64;

    // layer 0: x -> bufA (+ half shadow)
    k_agg<<<aggGrid, 256>>>();
    k_gemm_ln<<<gemmGrid, 256>>>(x, Wn, bn, Wr, gamma, beta, bufA, halfbuf);
    // layer 1: bufA -> bufB (+ half shadow)
    k_agg<<<aggGrid, 256>>>();
    k_gemm_ln<<<gemmGrid, 256>>>(bufA, Wn + 128 * 128, bn + 128, Wr + 128 * 128,
                                 gamma + 128, beta + 128, bufB, halfbuf);
    // layer 2: bufB -> out_node (no shadow needed)
    k_agg<<<aggGrid, 256>>>();
    k_gemm_ln<<<gemmGrid, 256>>>(bufB, Wn + 2 * 128 * 128, bn + 2 * 128,
                                 Wr + 2 * 128 * 128, gamma + 2 * 128, beta + 2 * 128,
                                 out_node, (__half*)nullptr);
    // pooling
    k_pool<<<(N_NODES + 63) / 64, 128>>>(out_node, batch, out_graph);
    k_div<<<(N_GRAPHS * HID + 255) / 256, 256>>>(out_graph);
}

// round 14
// speedup vs baseline: 3.2794x; 2.2130x over previous
#include <cuda_runtime.h>
#include <cuda_bf16.h>
#include <cuda_fp16.h>

#define N_NODES 50000
#define N_EDGES 1600000
#define HID 128
#define N_GRAPHS 64
#define LN_EPS 1e-5f
#define NBLK ((N_NODES + 255) / 256)   // 196

// ---------------- device scratch (static, no allocation) ----------------
__device__ int    g_deg[N_NODES];
__device__ int    g_rowstart[N_NODES + 1];
__device__ int    g_cursor[N_NODES];
__device__ int    g_csr[N_EDGES];
__device__ float  g_invdeg[N_NODES];
__device__ __half g_aggh[N_NODES * HID];       // fp16 neighbor-mean
__device__ __half g_half[N_NODES * HID];       // fp16 shadow of current layer input
__device__ __half g_wh[3 * 2 * HID * HID];     // fp16 [layer][k=0..255][n] stacked Wn;Wr
__device__ float  g_cnt[N_GRAPHS];
__device__ int    g_blocksum[NBLK];

// ---------------- mma / ldmatrix helpers ----------------
#define LDSM_X4(r0, r1, r2, r3, a)                                             \
    asm volatile("ldmatrix.sync.aligned.m8n8.x4.shared.b16 {%0,%1,%2,%3},[%4];"\
                 : "=r"(r0), "=r"(r1), "=r"(r2), "=r"(r3) : "r"(a))
#define LDSM_X4T(r0, r1, r2, r3, a)                                            \
    asm volatile("ldmatrix.sync.aligned.m8n8.x4.trans.shared.b16 {%0,%1,%2,%3},[%4];"\
                 : "=r"(r0), "=r"(r1), "=r"(r2), "=r"(r3) : "r"(a))
#define MMA16816(c, a, b0, b1)                                                 \
    asm volatile("mma.sync.aligned.m16n8k16.row.col.f32.f16.f16.f32 "          \
                 "{%0,%1,%2,%3},{%4,%5,%6,%7},{%8,%9},{%0,%1,%2,%3};"          \
                 : "+f"((c)[0]), "+f"((c)[1]), "+f"((c)[2]), "+f"((c)[3])      \
                 : "r"((a)[0]), "r"((a)[1]), "r"((a)[2]), "r"((a)[3]),         \
                   "r"(b0), "r"(b1))

// ---------------- init ----------------
__global__ void k_init(float* dout_graph) {
    int i = blockIdx.x * blockDim.x + threadIdx.x;
    if (i < N_NODES) { g_deg[i] = 0; g_cursor[i] = 0; }
    if (i < N_GRAPHS * HID) dout_graph[i] = 0.f;
    if (i < N_GRAPHS) g_cnt[i] = 0.f;
}

// ---------------- fp32 -> fp16 convert (input x) ----------------
__global__ void k_cvt(const float* __restrict__ x) {
    int i = blockIdx.x * blockDim.x + threadIdx.x;  // 4 elements per thread
    if (i < N_NODES * HID / 4) {
        float4 v = ((const float4*)x)[i];
        __half2 h0 = __floats2half2_rn(v.x, v.y);
        __half2 h1 = __floats2half2_rn(v.z, v.w);
        uint2 p;
        p.x = *(unsigned*)&h0;
        p.y = *(unsigned*)&h1;
        ((uint2*)g_half)[i] = p;
    }
}

// ---------------- weights fp32 -> fp16 stacked [layer][256][128] ----------------
__global__ void k_cvtw(const float* __restrict__ Wn, const float* __restrict__ Wr) {
    int i = blockIdx.x * blockDim.x + threadIdx.x;  // 2 elements per thread
    if (i < 3 * 256 * 64) {
        int n2 = i & 63;
        int kk = (i >> 6) & 255;
        int L  = i >> 14;
        int col = n2 * 2;
        const float* srcp = (kk < 128) ? (Wn + L * 16384 + kk * 128 + col)
                                       : (Wr + L * 16384 + (kk - 128) * 128 + col);
        float2 v = *(const float2*)srcp;
        __half2 h = __floats2half2_rn(v.x, v.y);
        *(__half2*)&g_wh[L * 32768 + kk * 128 + col] = h;
    }
}

// ---------------- degree histogram (4 edges/thread) ----------------
__global__ void k_hist(const int* __restrict__ dst) {
    int i = blockIdx.x * blockDim.x + threadIdx.x;
    if (i < N_EDGES / 4) {
        int4 d = ((const int4*)dst)[i];
        atomicAdd(&g_deg[d.x], 1);
        atomicAdd(&g_deg[d.y], 1);
        atomicAdd(&g_deg[d.z], 1);
        atomicAdd(&g_deg[d.w], 1);
    }
}

// ---------------- scan stage 1 ----------------
__global__ void k_blocksum() {
    int b = blockIdx.x, t = threadIdx.x;
    int i = b * 256 + t;
    int v = (i < N_NODES) ? g_deg[i] : 0;
#pragma unroll
    for (int o = 16; o; o >>= 1) v += __shfl_down_sync(0xffffffffu, v, o);
    __shared__ int ws[8];
    if ((t & 31) == 0) ws[t >> 5] = v;
    __syncthreads();
    if (t < 8) {
        int s = ws[t];
#pragma unroll
        for (int o = 4; o; o >>= 1) s += __shfl_down_sync(0xffu, s, o);
        if (t == 0) g_blocksum[b] = s;
    }
}

// ---------------- scan stage 2 ----------------
__global__ void k_scanblocksums() {
    int t = threadIdx.x;
    int v = (t < NBLK) ? g_blocksum[t] : 0;
    int lane = t & 31, w = t >> 5;
    int s = v;
#pragma unroll
    for (int o = 1; o < 32; o <<= 1) {
        int u = __shfl_up_sync(0xffffffffu, s, o);
        if (lane >= o) s += u;
    }
    __shared__ int wsum[8];
    if (lane == 31) wsum[w] = s;
    __syncthreads();
    if (t < 8) {
        int x = wsum[t];
#pragma unroll
        for (int o = 1; o < 8; o <<= 1) {
            int u = __shfl_up_sync(0xffu, x, o);
            if (t >= o) x += u;
        }
        wsum[t] = x;
    }
    __syncthreads();
    int incl = s + (w ? wsum[w - 1] : 0);
    if (t < NBLK) g_blocksum[t] = incl - v;
}

// ---------------- scan stage 3 ----------------
__global__ void k_rowstart() {
    int b = blockIdx.x, t = threadIdx.x;
    int i = b * 256 + t;
    int v = (i < N_NODES) ? g_deg[i] : 0;
    if (i < N_NODES) g_invdeg[i] = 1.f / fmaxf((float)v, 1.f);
    int lane = t & 31, w = t >> 5;
    int s = v;
#pragma unroll
    for (int o = 1; o < 32; o <<= 1) {
        int u = __shfl_up_sync(0xffffffffu, s, o);
        if (lane >= o) s += u;
    }
    __shared__ int wsum[8];
    if (lane == 31) wsum[w] = s;
    __syncthreads();
    if (t < 8) {
        int x = wsum[t];
#pragma unroll
        for (int o = 1; o < 8; o <<= 1) {
            int u = __shfl_up_sync(0xffu, x, o);
            if (t >= o) x += u;
        }
        wsum[t] = x;
    }
    __syncthreads();
    int incl = s + (w ? wsum[w - 1] : 0) + g_blocksum[b];
    if (i < N_NODES) g_rowstart[i + 1] = incl;
    if (i == 0) g_rowstart[0] = 0;
}

// ---------------- CSR fill (4 edges/thread) ----------------
__global__ void k_fill(const int* __restrict__ src, const int* __restrict__ dst) {
    int i = blockIdx.x * blockDim.x + threadIdx.x;
    if (i < N_EDGES / 4) {
        int4 d = ((const int4*)dst)[i];
        int4 s = ((const int4*)src)[i];
        int p;
        p = atomicAdd(&g_cursor[d.x], 1); g_csr[g_rowstart[d.x] + p] = s.x;
        p = atomicAdd(&g_cursor[d.y], 1); g_csr[g_rowstart[d.y] + p] = s.y;
        p = atomicAdd(&g_cursor[d.z], 1); g_csr[g_rowstart[d.z] + p] = s.z;
        p = atomicAdd(&g_cursor[d.w], 1); g_csr[g_rowstart[d.w] + p] = s.w;
    }
}

// ---------------- mean-neighbor aggregation (fp16 in, fp32 acc, fp16 out) ----------------
__device__ __forceinline__ void acc4h(float4& a, uint2 p) {
    __half2 h0 = *(__half2*)&p.x;
    __half2 h1 = *(__half2*)&p.y;
    float2 f0 = __half22float2(h0);
    float2 f1 = __half22float2(h1);
    a.x += f0.x; a.y += f0.y; a.z += f1.x; a.w += f1.y;
}

__global__ void k_agg() {
    int gw = (blockIdx.x * blockDim.x + threadIdx.x) >> 5;
    int lane = threadIdx.x & 31;
    if (gw >= N_NODES) return;
    int beg = g_rowstart[gw], end = g_rowstart[gw + 1];
    const uint2* xh = (const uint2*)g_half;   // 32 uint2 per row
    float4 a0 = {0, 0, 0, 0}, a1 = a0, a2 = a0, a3 = a0;
    for (int e = beg; e < end; e += 32) {
        int n = (e + lane < end) ? g_csr[e + lane] : 0;
        int c = min(32, end - e);
        int j = 0;
        for (; j + 4 <= c; j += 4) {
            int s0 = __shfl_sync(0xffffffffu, n, j);
            int s1 = __shfl_sync(0xffffffffu, n, j + 1);
            int s2 = __shfl_sync(0xffffffffu, n, j + 2);
            int s3 = __shfl_sync(0xffffffffu, n, j + 3);
            uint2 v0 = xh[s0 * 32 + lane];
            uint2 v1 = xh[s1 * 32 + lane];
            uint2 v2 = xh[s2 * 32 + lane];
            uint2 v3 = xh[s3 * 32 + lane];
            acc4h(a0, v0); acc4h(a1, v1); acc4h(a2, v2); acc4h(a3, v3);
        }
        for (; j < c; j++) {
            int s0 = __shfl_sync(0xffffffffu, n, j);
            acc4h(a0, xh[s0 * 32 + lane]);
        }
    }
    float sc = g_invdeg[gw];
    __half2 h0 = __floats2half2_rn((a0.x + a1.x + a2.x + a3.x) * sc,
                                   (a0.y + a1.y + a2.y + a3.y) * sc);
    __half2 h1 = __floats2half2_rn((a0.z + a1.z + a2.z + a3.z) * sc,
                                   (a0.w + a1.w + a2.w + a3.w) * sc);
    uint2 p;
    p.x = *(unsigned*)&h0;
    p.y = *(unsigned*)&h1;
    ((uint2*)g_aggh)[gw * 32 + lane] = p;
}

// ---------------- tensor-core GEMM (K=256: [aggh;xh] @ Wh + bn) + LN + ReLU -------------
// CTA: 256 threads = 8 warps. Tile M=128, N=128, K=256 in 8 chunks of 32.
// warp (wm = wid&3, wn = wid>>2): rows wm*32..+31, cols wn*64..+63.
// A smem: [128][40] halves (80B stride, odd*16B -> ldmatrix conflict-free).
// B smem: [32][136] halves (272B stride, odd*16B -> trans ldmatrix conflict-free).
__global__ void __launch_bounds__(256) k_gemm_tc(
    const __half* __restrict__ Wh,
    const float* __restrict__ bnp,
    const float* __restrict__ gm, const float* __restrict__ bt,
    float* __restrict__ xout, __half* __restrict__ hout)
{
    __shared__ __half As[128 * 40];
    __shared__ __half Bs[32 * 136];
    __shared__ float red[128][2][2];   // [row][wn][sum, sumsq]

    int tid = threadIdx.x;
    int m0 = blockIdx.x * 128;
    int wid = tid >> 5, lane = tid & 31;
    int wm = wid & 3, wn = wid >> 2;

    float acc[2][8][4];
#pragma unroll
    for (int mf = 0; mf < 2; mf++)
#pragma unroll
        for (int nf = 0; nf < 8; nf++)
#pragma unroll
            for (int r = 0; r < 4; r++) acc[mf][nf][r] = 0.f;

    int ra = tid >> 2, qa = tid & 3;       // A loader: rows ra, ra+64; 16B piece qa
    int kb = tid >> 4, qb = tid & 15;      // B loader: rows kb, kb+16; 16B piece qb

    for (int kc = 0; kc < 8; kc++) {
        const __half* hbase = (kc < 4) ? (g_aggh + kc * 32) : (g_half + (kc - 4) * 32);
        // A chunk 128x32
#pragma unroll
        for (int h = 0; h < 2; h++) {
            int r = ra + h * 64;
            int row = m0 + r;
            uint4 v = {0, 0, 0, 0};
            if (row < N_NODES) v = *(const uint4*)(hbase + row * 128 + qa * 8);
            *(uint4*)&As[r * 40 + qa * 8] = v;
        }
        // B chunk 32x128
#pragma unroll
        for (int h = 0; h < 2; h++) {
            int k = kb + h * 16;
            uint4 v = *(const uint4*)(Wh + (kc * 32 + k) * 128 + qb * 8);
            *(uint4*)&Bs[k * 136 + qb * 8] = v;
        }
        __syncthreads();

#pragma unroll
        for (int ks = 0; ks < 2; ks++) {
            unsigned a[2][4];
#pragma unroll
            for (int mf = 0; mf < 2; mf++) {
                unsigned ad = (unsigned)__cvta_generic_to_shared(
                    &As[(wm * 32 + mf * 16 + (lane & 15)) * 40 + ks * 16 + (lane >> 4) * 8]);
                LDSM_X4(a[mf][0], a[mf][1], a[mf][2], a[mf][3], ad);
            }
            unsigned b[4][4];
#pragma unroll
            for (int nf4 = 0; nf4 < 4; nf4++) {
                unsigned ad = (unsigned)__cvta_generic_to_shared(
                    &Bs[(ks * 16 + (lane & 15)) * 136 + wn * 64 + nf4 * 16 + (lane >> 4) * 8]);
                LDSM_X4T(b[nf4][0], b[nf4][1], b[nf4][2], b[nf4][3], ad);
            }
#pragma unroll
            for (int mf = 0; mf < 2; mf++)
#pragma unroll
                for (int nf4 = 0; nf4 < 4; nf4++) {
                    MMA16816(acc[mf][nf4 * 2],     a[mf], b[nf4][0], b[nf4][1]);
                    MMA16816(acc[mf][nf4 * 2 + 1], a[mf], b[nf4][2], b[nf4][3]);
                }
        }
        __syncthreads();
    }

    // ---------------- epilogue: +bn, LN (fp32), ReLU, store fp32/fp16 ----------------
    int q = lane >> 2, t4 = lane & 3;
    float2 bnv[8], gv[8], bv[8];
#pragma unroll
    for (int nf = 0; nf < 8; nf++) {
        int col = wn * 64 + nf * 8 + 2 * t4;
        bnv[nf] = *(const float2*)&bnp[col];
        gv[nf]  = *(const float2*)&gm[col];
        bv[nf]  = *(const float2*)&bt[col];
    }
#pragma unroll
    for (int mf = 0; mf < 2; mf++)
#pragma unroll
        for (int h = 0; h < 2; h++) {
            float s = 0.f, sq = 0.f;
#pragma unroll
            for (int nf = 0; nf < 8; nf++) {
                float v0 = acc[mf][nf][2 * h]     + bnv[nf].x;
                float v1 = acc[mf][nf][2 * h + 1] + bnv[nf].y;
                acc[mf][nf][2 * h] = v0;
                acc[mf][nf][2 * h + 1] = v1;
                s += v0 + v1;
                sq += v0 * v0 + v1 * v1;
            }
            s  += __shfl_xor_sync(0xffffffffu, s, 1);
            s  += __shfl_xor_sync(0xffffffffu, s, 2);
            sq += __shfl_xor_sync(0xffffffffu, sq, 1);
            sq += __shfl_xor_sync(0xffffffffu, sq, 2);
            int row = wm * 32 + mf * 16 + q + 8 * h;
            if (t4 == 0) { red[row][wn][0] = s; red[row][wn][1] = sq; }
        }
    __syncthreads();
#pragma unroll
    for (int mf = 0; mf < 2; mf++)
#pragma unroll
        for (int h = 0; h < 2; h++) {
            int row = wm * 32 + mf * 16 + q + 8 * h;
            int grow = m0 + row;
            float tot  = red[row][0][0] + red[row][1][0];
            float totq = red[row][0][1] + red[row][1][1];
            float mean = tot * (1.f / 128.f);
            float var  = totq * (1.f / 128.f) - mean * mean;
            float rstd = rsqrtf(fmaxf(var, 0.f) + LN_EPS);
            if (grow < N_NODES) {
#pragma unroll
                for (int nf = 0; nf < 8; nf++) {
                    float o0 = fmaxf((acc[mf][nf][2 * h] - mean) * rstd * gv[nf].x + bv[nf].x, 0.f);
                    float o1 = fmaxf((acc[mf][nf][2 * h + 1] - mean) * rstd * gv[nf].y + bv[nf].y, 0.f);
                    int col = wn * 64 + nf * 8 + 2 * t4;
                    if (xout) {
                        float2 o = {o0, o1};
                        *(float2*)&xout[grow * 128 + col] = o;
                    }
                    if (hout) {
                        __half2 hh = __floats2half2_rn(o0, o1);
                        *(__half2*)&hout[grow * 128 + col] = hh;
                    }
                }
            }
        }
}

// ---------------- graph mean pool ----------------
__global__ void k_pool(const float* __restrict__ node, const int* __restrict__ batch,
                       float* __restrict__ gsum) {
    int f = threadIdx.x;  // 128
    int n0 = blockIdx.x * 64;
    if (n0 >= N_NODES) return;
    int n1 = min(n0 + 64, N_NODES);
    float acc = 0.f;
    int cnt = 0;
    int cur = batch[n0];
    for (int n = n0; n < n1; n++) {
        int b = batch[n];
        if (b != cur) {
            atomicAdd(&gsum[cur * 128 + f], acc);
            if (f == 0) atomicAdd(&g_cnt[cur], (float)cnt);
            acc = 0.f; cnt = 0; cur = b;
        }
        acc += node[n * 128 + f];
        cnt++;
    }
    atomicAdd(&gsum[cur * 128 + f], acc);
    if (f == 0) atomicAdd(&g_cnt[cur], (float)cnt);
}

__global__ void k_div(float* __restrict__ gout) {
    int i = blockIdx.x * blockDim.x + threadIdx.x;
    if (i < N_GRAPHS * HID) {
        int g = i >> 7;
        gout[i] = gout[i] / fmaxf(g_cnt[g], 1.f);
    }
}

// ---------------- launch ----------------
extern "C" void kernel_launch(void* const* d_in, const int* in_sizes, int n_in,
                              void* d_out, int out_size) {
    const float* x     = (const float*)d_in[0];
    const float* Wn    = (const float*)d_in[1];
    const float* bn    = (const float*)d_in[2];
    const float* Wr    = (const float*)d_in[3];
    const float* gamma = (const float*)d_in[4];
    const float* beta  = (const float*)d_in[5];
    const int*   ei    = (const int*)d_in[6];
    const int*   batch = (const int*)d_in[7];
    float* out = (float*)d_out;

    float* out_graph = out;                    // [64, 128]
    float* out_node  = out + N_GRAPHS * HID;   // [50000, 128]

    const int* src = ei;
    const int* dst = ei + N_EDGES;

    __half *halfbuf, *whbuf;
    cudaGetSymbolAddress((void**)&halfbuf, g_half);
    cudaGetSymbolAddress((void**)&whbuf, g_wh);

    // CSR build + fp16 shadows
    k_init<<<(N_NODES + 255) / 256, 256>>>(out_graph);
    k_cvt<<<(N_NODES * HID / 4 + 255) / 256, 256>>>(x);
    k_cvtw<<<(3 * 256 * 64 + 255) / 256, 256>>>(Wn, Wr);
    k_hist<<<(N_EDGES / 4 + 255) / 256, 256>>>(dst);
    k_blocksum<<<NBLK, 256>>>();
    k_scanblocksums<<<1, 256>>>();
    k_rowstart<<<NBLK, 256>>>();
    k_fill<<<(N_EDGES / 4 + 255) / 256, 256>>>(src, dst);

    int aggGrid  = (N_NODES * 32 + 255) / 256;   // warp per node
    int gemmGrid = (N_NODES + 127) / 128;        // 391

    // layer 0: reads g_half(x) + g_aggh -> writes g_half (in-place by M-tile, safe)
    k_agg<<<aggGrid, 256>>>();
    k_gemm_tc<<<gemmGrid, 256>>>(whbuf, bn, gamma, beta, (float*)nullptr, halfbuf);
    // layer 1
    k_agg<<<aggGrid, 256>>>();
    k_gemm_tc<<<gemmGrid, 256>>>(whbuf + 32768, bn + 128, gamma + 128, beta + 128,
                                 (float*)nullptr, halfbuf);
    // layer 2: fp32 node embeddings to output
    k_agg<<<aggGrid, 256>>>();
    k_gemm_tc<<<gemmGrid, 256>>>(whbuf + 65536, bn + 256, gamma + 256, beta + 256,
                                 out_node, (__half*)nullptr);
    // pooling
    k_pool<<<(N_NODES + 63) / 64, 128>>>(out_node, batch, out_graph);
    k_div<<<(N_GRAPHS * HID + 255) / 256, 256>>>(out_graph);
}